// round 4
// baseline (speedup 1.0000x reference)
#include <cuda_runtime.h>
#include <cstdint>

// GeneralConv: out[i] += W[k] @ x[j] over 2M edges, G=4 groups of 16->16, + bias.
//
// Inputs (metadata order):
//  0: input  float32 [100000*64]
//  1: i      int32   [E]
//  2: j      int32   [E]
//  3: k      int32   [E]
//  4: n      int32   [1]      (unused; derived from in_sizes)
//  5: weight float32 [64*16*27]   (in_c, out_c/g, K)
//  6: bias   float32 [64]
// out: float32 [100000*64]

#define THREADS 512
static constexpr int WS_FLOATS = 27 * 16 * 64;        // 27648 floats
static constexpr int SMEM_BYTES = WS_FLOATS * 4;      // 110592 B

__global__ void init_bias_kernel(float* __restrict__ out,
                                 const float* __restrict__ bias,
                                 int total) {
    int idx = blockIdx.x * blockDim.x + threadIdx.x;
    if (idx < total) out[idx] = bias[idx & 63];
}

// Half-warp per edge. Lane t (0..15) owns output channels 4t..4t+3
// (group g = t>>2, d = (4t&15)..). Weights staged in smem as
// ws[(k*16 + c)*64 + ch] so the per-c weight read is a contiguous LDS.128.
// x row loaded as one float4 per lane, redistributed via static shfl.
__global__ __launch_bounds__(THREADS, 2)
void edge_kernel(const float* __restrict__ x,
                 const int*   __restrict__ ei,
                 const int*   __restrict__ ej,
                 const int*   __restrict__ ek,
                 const float* __restrict__ weight,
                 float*       __restrict__ out,
                 int E) {
    extern __shared__ float ws[];

    // Re-layout weights: ws[(kk*16+c)*64 + g*16+d] = weight[(g*16+c)*432 + d*27 + kk]
    for (int idx = threadIdx.x; idx < WS_FLOATS; idx += THREADS) {
        int ch   = idx & 63;        // g*16 + d
        int rest = idx >> 6;        // kk*16 + c
        int c    = rest & 15;
        int kk   = rest >> 4;
        int g    = ch >> 4;
        int d    = ch & 15;
        ws[idx] = weight[(g * 16 + c) * 432 + d * 27 + kk];
    }
    __syncthreads();

    const int t  = threadIdx.x & 15;           // lane within half-warp
    const int hw = threadIdx.x >> 4;           // half-warp id within block (0..31)
    const unsigned hmask = 0xFFFFu << (threadIdx.x & 16);
    const int g = t >> 2;

    const int nchunks = (E + 15) >> 4;         // 16 edges per half-warp chunk
    int       chunk   = blockIdx.x * (THREADS / 16) + hw;
    const int cstride = gridDim.x * (THREADS / 16);

    for (; chunk < nchunks; chunk += cstride) {
        const long long eb  = (long long)chunk << 4;
        const int       cnt = (int)((E - eb) < 16 ? (E - eb) : 16);

        // prologue: load edge 0 of this chunk
        int jc = ej[eb];
        int kc = ek[eb];
        int ic = ei[eb];
        float4 xv = *reinterpret_cast<const float4*>(x + (long long)jc * 64 + (t << 2));

        for (int it = 0; it < cnt; ++it) {
            // branch-free prefetch of next edge (clamped; always in-bounds)
            const long long enx = eb + (it + 1 < cnt ? it + 1 : cnt - 1);
            int jn  = ej[enx];
            int kn  = ek[enx];
            int in_ = ei[enx];
            float4 xn = *reinterpret_cast<const float4*>(
                x + (long long)jn * 64 + (t << 2));

            const float* wk = ws + ((kc << 4) << 6);   // ws + kc*16*64
            float4 acc = make_float4(0.f, 0.f, 0.f, 0.f);

#pragma unroll
            for (int c = 0; c < 16; ++c) {
                // x[g*16 + c]: lives in lane (g*4 + c/4), component c%4 (static)
                const int src = (g << 2) + (c >> 2);
                float xc;
                switch (c & 3) {
                    case 0:  xc = __shfl_sync(hmask, xv.x, src, 16); break;
                    case 1:  xc = __shfl_sync(hmask, xv.y, src, 16); break;
                    case 2:  xc = __shfl_sync(hmask, xv.z, src, 16); break;
                    default: xc = __shfl_sync(hmask, xv.w, src, 16); break;
                }
                const float4 wv =
                    *reinterpret_cast<const float4*>(wk + c * 64 + (t << 2));
                acc.x = fmaf(xc, wv.x, acc.x);
                acc.y = fmaf(xc, wv.y, acc.y);
                acc.z = fmaf(xc, wv.z, acc.z);
                acc.w = fmaf(xc, wv.w, acc.w);
            }

            float* dst = out + (long long)ic * 64 + (t << 2);
            asm volatile("red.global.add.v4.f32 [%0], {%1, %2, %3, %4};"
                         :: "l"(dst), "f"(acc.x), "f"(acc.y), "f"(acc.z), "f"(acc.w)
                         : "memory");

            xv = xn; jc = jn; kc = kn; ic = in_;
        }
    }
}

extern "C" void kernel_launch(void* const* d_in, const int* in_sizes, int n_in,
                              void* d_out, int out_size) {
    const float* x  = (const float*)d_in[0];
    const int*   ei = (const int*)d_in[1];
    const int*   ej = (const int*)d_in[2];
    const int*   ek = (const int*)d_in[3];
    const float* w  = (const float*)d_in[5];
    const float* b  = (const float*)d_in[6];
    float*       out = (float*)d_out;

    const int E     = in_sizes[1];
    const int total = out_size;  // N * 64

    init_bias_kernel<<<(total + 255) / 256, 256>>>(out, b, total);

    int dev = 0, sms = 148;
    cudaGetDevice(&dev);
    cudaDeviceGetAttribute(&sms, cudaDevAttrMultiProcessorCount, dev);

    cudaFuncSetAttribute(edge_kernel,
                         cudaFuncAttributeMaxDynamicSharedMemorySize, SMEM_BYTES);
    edge_kernel<<<2 * sms, THREADS, SMEM_BYTES>>>(x, ei, ej, ek, w, out, E);
}

// round 7
// speedup vs baseline: 1.2527x; 1.2527x over previous
#include <cuda_runtime.h>
#include <cstdint>

// GeneralConv: out[i] += W[k] @ x[j], E=2M edges, G=4 groups 16->16, + bias.
// Strategy: counting-sort edges by k (27 bins), then warp-per-edge compute with
// register-resident weights per k-segment, FFMA2 (f32x2) math, red.v2 scatter.
//
// Inputs: 0 input f32[100000*64], 1 i i32[E], 2 j i32[E], 3 k i32[E],
//         4 n i32[1], 5 weight f32[64*16*27], 6 bias f32[64]; out f32[100000*64]

static constexpr int CAP = 2200000;   // max edges supported by scratch

__device__ int2 g_pij[CAP];           // permuted (i, j)
__device__ int  g_pk[CAP];            // permuted k
__device__ int  g_counts[27];
__device__ int  g_offsets[28];
__device__ int  g_cursor[27];

__global__ void init_bias_kernel(float* __restrict__ out,
                                 const float* __restrict__ bias, int total) {
    int idx = blockIdx.x * blockDim.x + threadIdx.x;
    if (idx < total) out[idx] = bias[idx & 63];
}

__global__ void zero_counts_kernel() {
    if (threadIdx.x < 27) g_counts[threadIdx.x] = 0;
}

__global__ void hist_kernel(const int* __restrict__ ek, int E) {
    __shared__ int c[27];
    if (threadIdx.x < 27) c[threadIdx.x] = 0;
    __syncthreads();
    for (int e = blockIdx.x * blockDim.x + threadIdx.x; e < E;
         e += gridDim.x * blockDim.x)
        atomicAdd(&c[ek[e]], 1);
    __syncthreads();
    if (threadIdx.x < 27) atomicAdd(&g_counts[threadIdx.x], c[threadIdx.x]);
}

__global__ void scan_kernel() {
    if (threadIdx.x == 0) {
        int s = 0;
        for (int b = 0; b < 27; ++b) {
            g_offsets[b] = s; g_cursor[b] = s; s += g_counts[b];
        }
        g_offsets[27] = s;
    }
}

#define SCATTER_SEG 16384
__global__ void scatter_kernel(const int* __restrict__ ei,
                               const int* __restrict__ ej,
                               const int* __restrict__ ek, int E) {
    __shared__ int lc[27], lbase[27];
    const int b0 = blockIdx.x * SCATTER_SEG;
    const int b1 = min(E, b0 + SCATTER_SEG);
    if (threadIdx.x < 27) lc[threadIdx.x] = 0;
    __syncthreads();
    for (int e = b0 + threadIdx.x; e < b1; e += blockDim.x)
        atomicAdd(&lc[ek[e]], 1);
    __syncthreads();
    if (threadIdx.x < 27) {
        lbase[threadIdx.x] = atomicAdd(&g_cursor[threadIdx.x], lc[threadIdx.x]);
        lc[threadIdx.x] = 0;
    }
    __syncthreads();
    for (int e = b0 + threadIdx.x; e < b1; e += blockDim.x) {
        int kk = ek[e];
        int p  = lbase[kk] + atomicAdd(&lc[kk], 1);
        g_pij[p] = make_int2(ei[e], ej[e]);
        g_pk[p]  = kk;
    }
}

#define FMA2(acc, a, b) \
    asm("fma.rn.f32x2 %0, %1, %2, %0;" : "+l"(acc) : "l"(a), "l"(b))
#define PACK2(dst, lo, hi) \
    asm("mov.b64 %0, {%1, %2};" : "=l"(dst) : "f"(lo), "f"(hi))
#define BCAST2(dst, v) \
    asm("mov.b64 %0, {%1, %1};" : "=l"(dst) : "f"(v))

// Warp per edge. Lane t owns out channels {2t, 2t+1}; g = t>>3, d0 = (2t)&15.
// Within a k-segment (edges sorted by k), the 16 weight f32x2 pairs live in
// registers. Per edge: 4 broadcast LDG.128 (x slice), 16 FFMA2, 1 RED.v2.
__global__ __launch_bounds__(256)
void compute_kernel(const float* __restrict__ x,
                    const float* __restrict__ weight,
                    float* __restrict__ out, int E, int nwarps) {
    const int wid = (blockIdx.x * blockDim.x + threadIdx.x) >> 5;
    const int t   = threadIdx.x & 31;
    const int g   = t >> 3;
    const int d0  = (2 * t) & 15;

    const int per = (E + nwarps - 1) / nwarps;
    int pos = wid * per;
    const int end = min(E, pos + per);
    const float* xg = x + g * 16;   // group-local x slice base

    while (pos < end) {
        const int kk   = g_pk[pos];
        const int send = min(end, g_offsets[kk + 1]);

        // Load this lane's 16 weight pairs for kernel-position kk.
        unsigned long long w2[16];
        const float* wb = weight + (g * 16) * 432 + d0 * 27 + kk;
#pragma unroll
        for (int c = 0; c < 16; ++c) {
            float lo = __ldg(wb + c * 432);
            float hi = __ldg(wb + c * 432 + 27);
            PACK2(w2[c], lo, hi);
        }

        // Software pipeline: indices 2 ahead, x row 1 ahead.
        int2 ij0 = g_pij[pos];
        int2 ij1 = g_pij[min(pos + 1, send - 1)];
        const float* xr0 = xg + (long long)ij0.y * 64;
        float4 cx0 = *(const float4*)(xr0 + 0);
        float4 cx1 = *(const float4*)(xr0 + 4);
        float4 cx2 = *(const float4*)(xr0 + 8);
        float4 cx3 = *(const float4*)(xr0 + 12);

        for (int e = pos; e < send; ++e) {
            const float* xrn = xg + (long long)ij1.y * 64;
            float4 nx0 = *(const float4*)(xrn + 0);
            float4 nx1 = *(const float4*)(xrn + 4);
            float4 nx2 = *(const float4*)(xrn + 8);
            float4 nx3 = *(const float4*)(xrn + 12);
            int2 ij2 = g_pij[min(e + 2, send - 1)];

            unsigned long long accA = 0ull, accB = 0ull;
#pragma unroll
            for (int q = 0; q < 4; ++q) {
                float4 v = (q == 0) ? cx0 : (q == 1) ? cx1 : (q == 2) ? cx2 : cx3;
                unsigned long long x2;
                BCAST2(x2, v.x); FMA2(accA, x2, w2[4 * q + 0]);
                BCAST2(x2, v.y); FMA2(accB, x2, w2[4 * q + 1]);
                BCAST2(x2, v.z); FMA2(accA, x2, w2[4 * q + 2]);
                BCAST2(x2, v.w); FMA2(accB, x2, w2[4 * q + 3]);
            }
            unsigned long long accT;
            asm("add.rn.f32x2 %0, %1, %2;" : "=l"(accT) : "l"(accA), "l"(accB));
            float r0, r1;
            asm("mov.b64 {%0, %1}, %2;" : "=f"(r0), "=f"(r1) : "l"(accT));

            float* dst = out + (long long)ij0.x * 64 + 2 * t;
            asm volatile("red.global.add.v2.f32 [%0], {%1, %2};"
                         :: "l"(dst), "f"(r0), "f"(r1) : "memory");

            ij0 = ij1; ij1 = ij2;
            cx0 = nx0; cx1 = nx1; cx2 = nx2; cx3 = nx3;
        }
        pos = send;
    }
}

extern "C" void kernel_launch(void* const* d_in, const int* in_sizes, int n_in,
                              void* d_out, int out_size) {
    const float* x  = (const float*)d_in[0];
    const int*   ei = (const int*)d_in[1];
    const int*   ej = (const int*)d_in[2];
    const int*   ek = (const int*)d_in[3];
    const float* w  = (const float*)d_in[5];
    const float* b  = (const float*)d_in[6];
    float*       out = (float*)d_out;

    const int E     = in_sizes[1];
    const int total = out_size;

    int dev = 0, sms = 148;
    cudaGetDevice(&dev);
    cudaDeviceGetAttribute(&sms, cudaDevAttrMultiProcessorCount, dev);

    init_bias_kernel<<<(total + 255) / 256, 256>>>(out, b, total);

    zero_counts_kernel<<<1, 32>>>();
    hist_kernel<<<2 * sms, 256>>>(ek, E);
    scan_kernel<<<1, 32>>>();
    scatter_kernel<<<(E + SCATTER_SEG - 1) / SCATTER_SEG, 256>>>(ei, ej, ek, E);

    const int grid   = 3 * sms;
    const int nwarps = grid * (256 / 32);
    compute_kernel<<<grid, 256>>>(x, w, out, E, nwarps);
}

// round 8
// speedup vs baseline: 1.6107x; 1.2857x over previous
#include <cuda_runtime.h>
#include <cstdint>

// GeneralConv: out[i] += W[k] @ x[j], E=2M, G=4 groups 16->16, + bias.
// R8: deterministic-base counting sort (blockhist->scan->scatter, 1 data pass),
// compute with input-channel-paired FFMA2 (zero packing movs in inner loop),
// k derived from g_offsets (no g_pk array). Exactly 4 launches.

static constexpr int CAP = 2200000;
static constexpr int SEG = 16384;
static constexpr int MAXB = (CAP + SEG - 1) / SEG + 1;   // max scatter blocks

__device__ int2 g_pij[CAP];            // k-sorted (i, j)
__device__ int  g_bc[MAXB * 27];       // per-block bin counts
__device__ int  g_bbase[MAXB * 27];    // per-block bin base offsets
__device__ int  g_offsets[28];         // global bin offsets

// Launch 0: per-block k-histogram, fused with out = bias init.
__global__ void blockhist_kernel(const int* __restrict__ ek, int E,
                                 float* __restrict__ out,
                                 const float* __restrict__ bias, int total) {
    __shared__ int c[27];
    if (threadIdx.x < 27) c[threadIdx.x] = 0;
    __syncthreads();
    const int b0 = blockIdx.x * SEG;
    const int b1 = min(E, b0 + SEG);
    for (int e = b0 + threadIdx.x; e < b1; e += blockDim.x)
        atomicAdd(&c[ek[e]], 1);
    // fused output init (grid-stride over all out elements)
    for (int idx = blockIdx.x * blockDim.x + threadIdx.x; idx < total;
         idx += gridDim.x * blockDim.x)
        out[idx] = bias[idx & 63];
    __syncthreads();
    if (threadIdx.x < 27) g_bc[blockIdx.x * 27 + threadIdx.x] = c[threadIdx.x];
}

// Launch 1: column scan. Thread k scans its bin over blocks; then bin prefix.
__global__ void scan_kernel(int nblocks) {
    __shared__ int tot[27];
    const int k = threadIdx.x;
    if (k < 27) {
        int s = 0;
        for (int b = 0; b < nblocks; ++b) {
            g_bbase[b * 27 + k] = s;
            s += g_bc[b * 27 + k];
        }
        tot[k] = s;
    }
    __syncthreads();
    if (k == 0) {
        int s = 0;
        for (int b = 0; b < 27; ++b) { g_offsets[b] = s; s += tot[b]; }
        g_offsets[27] = s;
    }
    __syncthreads();
    if (k < 27) {
        int base = g_offsets[k];
        for (int b = 0; b < nblocks; ++b) g_bbase[b * 27 + k] += base;
    }
}

// Launch 2: single-pass scatter with deterministic per-block bases.
__global__ void scatter_kernel(const int* __restrict__ ei,
                               const int* __restrict__ ej,
                               const int* __restrict__ ek, int E) {
    __shared__ int base[27], lc[27];
    if (threadIdx.x < 27) {
        base[threadIdx.x] = g_bbase[blockIdx.x * 27 + threadIdx.x];
        lc[threadIdx.x] = 0;
    }
    __syncthreads();
    const int b0 = blockIdx.x * SEG;
    const int b1 = min(E, b0 + SEG);
    for (int e = b0 + threadIdx.x; e < b1; e += blockDim.x) {
        int kk = ek[e];
        int p  = base[kk] + atomicAdd(&lc[kk], 1);
        g_pij[p] = make_int2(ei[e], ej[e]);
    }
}

#define FMA2(acc, a, b) \
    asm("fma.rn.f32x2 %0, %1, %2, %0;" : "+l"(acc) : "l"(a), "l"(b))
#define PACK2(dst, lo, hi) \
    asm("mov.b64 %0, {%1, %2};" : "=l"(dst) : "f"(lo), "f"(hi))

// Launch 3: warp per edge. Lane t owns out channels {d0, d0+1} of group g=t>>3.
// f32x2 pairs run over INPUT channel pairs (2p, 2p+1): x pairs come directly
// from 16B loads (ulonglong2) — no packing movs in the inner loop. Weight
// pairs packed once per k-segment. Horizontal add at the end.
__global__ __launch_bounds__(256)
void compute_kernel(const float* __restrict__ x,
                    const float* __restrict__ weight,
                    float* __restrict__ out, int E, int nwarps) {
    const int wid = (blockIdx.x * blockDim.x + threadIdx.x) >> 5;
    const int t   = threadIdx.x & 31;
    const int g   = t >> 3;
    const int d0  = (2 * t) & 15;

    const int per = (E + nwarps - 1) / nwarps;
    int pos = wid * per;
    const int end = min(E, pos + per);
    const float* xg = x + g * 16;

    while (pos < end) {
        // derive k for this segment: g_offsets[kk] <= pos < g_offsets[kk+1]
        int kk = 0;
        while (g_offsets[kk + 1] <= pos) ++kk;
        const int send = min(end, g_offsets[kk + 1]);

        // Pack weights: wA[p] = (w[2p][d0], w[2p+1][d0]), wB for d0+1.
        unsigned long long wA[8], wB[8];
        const float* wb = weight + (g * 16) * 432 + d0 * 27 + kk;
#pragma unroll
        for (int p = 0; p < 8; ++p) {
            float a0 = __ldg(wb + (2 * p) * 432);
            float a1 = __ldg(wb + (2 * p + 1) * 432);
            PACK2(wA[p], a0, a1);
            float b0 = __ldg(wb + (2 * p) * 432 + 27);
            float b1 = __ldg(wb + (2 * p + 1) * 432 + 27);
            PACK2(wB[p], b0, b1);
        }

        // Software pipeline: indices 2 ahead, x row 1 ahead.
        int2 ij0 = g_pij[pos];
        int2 ij1 = g_pij[min(pos + 1, send - 1)];
        const ulonglong2* xr = (const ulonglong2*)(xg + (long long)ij0.y * 64);
        ulonglong2 cx0 = xr[0], cx1 = xr[1], cx2 = xr[2], cx3 = xr[3];

        for (int e = pos; e < send; ++e) {
            const ulonglong2* xn = (const ulonglong2*)(xg + (long long)ij1.y * 64);
            ulonglong2 nx0 = xn[0], nx1 = xn[1], nx2 = xn[2], nx3 = xn[3];
            int2 ij2 = g_pij[min(e + 2, send - 1)];

            unsigned long long accA = 0ull, accB = 0ull;
            FMA2(accA, cx0.x, wA[0]); FMA2(accB, cx0.x, wB[0]);
            FMA2(accA, cx0.y, wA[1]); FMA2(accB, cx0.y, wB[1]);
            FMA2(accA, cx1.x, wA[2]); FMA2(accB, cx1.x, wB[2]);
            FMA2(accA, cx1.y, wA[3]); FMA2(accB, cx1.y, wB[3]);
            FMA2(accA, cx2.x, wA[4]); FMA2(accB, cx2.x, wB[4]);
            FMA2(accA, cx2.y, wA[5]); FMA2(accB, cx2.y, wB[5]);
            FMA2(accA, cx3.x, wA[6]); FMA2(accB, cx3.x, wB[6]);
            FMA2(accA, cx3.y, wA[7]); FMA2(accB, cx3.y, wB[7]);

            float a_lo, a_hi, b_lo, b_hi;
            asm("mov.b64 {%0, %1}, %2;" : "=f"(a_lo), "=f"(a_hi) : "l"(accA));
            asm("mov.b64 {%0, %1}, %2;" : "=f"(b_lo), "=f"(b_hi) : "l"(accB));
            float r0 = a_lo + a_hi;
            float r1 = b_lo + b_hi;

            float* dst = out + (long long)ij0.x * 64 + 2 * t;
            asm volatile("red.global.add.v2.f32 [%0], {%1, %2};"
                         :: "l"(dst), "f"(r0), "f"(r1) : "memory");

            ij0 = ij1; ij1 = ij2;
            cx0 = nx0; cx1 = nx1; cx2 = nx2; cx3 = nx3;
        }
        pos = send;
    }
}

extern "C" void kernel_launch(void* const* d_in, const int* in_sizes, int n_in,
                              void* d_out, int out_size) {
    const float* x  = (const float*)d_in[0];
    const int*   ei = (const int*)d_in[1];
    const int*   ej = (const int*)d_in[2];
    const int*   ek = (const int*)d_in[3];
    const float* w  = (const float*)d_in[5];
    const float* b  = (const float*)d_in[6];
    float*       out = (float*)d_out;

    const int E     = in_sizes[1];
    const int total = out_size;
    const int nblocks = (E + SEG - 1) / SEG;

    int dev = 0, sms = 148;
    cudaGetDevice(&dev);
    cudaDeviceGetAttribute(&sms, cudaDevAttrMultiProcessorCount, dev);

    blockhist_kernel<<<nblocks, 256>>>(ek, E, out, b, total);
    scan_kernel<<<1, 32>>>(nblocks);
    scatter_kernel<<<nblocks, 256>>>(ei, ej, ek, E);

    const int grid   = 3 * sms;
    const int nwarps = grid * (256 / 32);
    compute_kernel<<<grid, 256>>>(x, w, out, E, nwarps);
}